// round 3
// baseline (speedup 1.0000x reference)
#include <cuda_runtime.h>

#define HWD   256
#define HW2   65536            // HWD*HWD
#define NB    8
#define NC    64
#define NPIX  (NB*HW2)         // 524288
#define HW24  16384            // HW2/4
#define BPC   2                // batches per chunk (67 MB of x per chunk < 126 MB L2)
#define NCHUNK (NB/BPC)        // 4
#define CQ    (BPC*HW24)       // pixel-quads per chunk = 32768
#define CPIX  (BPC*HW2)        // pixels per chunk     = 131072

// Scratch (static device globals — allocation-free)
__device__ float g_n1[NPIX];
__device__ float g_n2[NPIX];
__device__ float g_r1[NPIX];

// ---------------------------------------------------------------------------
// K1 (per chunk): per-pixel channel L1 norms of x1 and x2.
// 4-way channel split within a block (64 pixel-quads x 4 groups of 16 ch),
// smem combine -> keeps per-chunk grid at 512 CTAs for full SM coverage.
// x reads use default caching so the chunk stays L2-resident for K3.
// ---------------------------------------------------------------------------
__global__ __launch_bounds__(256) void k_norm(const float4* __restrict__ x1,
                                              const float4* __restrict__ x2,
                                              int batch0) {
    __shared__ float4 sm1[4][64];
    __shared__ float4 sm2[4][64];
    int t = threadIdx.x;
    int p = t & 63;                 // pixel-quad within block
    int g = t >> 6;                 // channel group 0..3
    int q = blockIdx.x * 64 + p;    // [0, CQ)
    int bl  = q >> 14;              // / HW24
    int hw4 = q & (HW24 - 1);
    size_t base = ((size_t)(batch0 + bl) * NC + g * 16) * HW24 + hw4;
    const float4* p1 = x1 + base;
    const float4* p2 = x2 + base;

    float4 s1 = make_float4(0.f, 0.f, 0.f, 0.f);
    float4 s2 = make_float4(0.f, 0.f, 0.f, 0.f);
#pragma unroll 4
    for (int c = 0; c < 16; ++c) {
        float4 a = p1[(size_t)c * HW24];
        float4 d = p2[(size_t)c * HW24];
        s1.x += fabsf(a.x); s1.y += fabsf(a.y); s1.z += fabsf(a.z); s1.w += fabsf(a.w);
        s2.x += fabsf(d.x); s2.y += fabsf(d.y); s2.z += fabsf(d.z); s2.w += fabsf(d.w);
    }
    sm1[g][p] = s1;
    sm2[g][p] = s2;
    __syncthreads();

    if (t < 64) {
        float4 a = sm1[0][t], b = sm1[1][t], c = sm1[2][t], d = sm1[3][t];
        float4 o;
        o.x = (a.x + b.x) + (c.x + d.x);
        o.y = (a.y + b.y) + (c.y + d.y);
        o.z = (a.z + b.z) + (c.z + d.z);
        o.w = (a.w + b.w) + (c.w + d.w);
        int qq = blockIdx.x * 64 + t;
        int b2 = qq >> 14, h2 = qq & (HW24 - 1);
        reinterpret_cast<float4*>(g_n1)[(batch0 + b2) * HW24 + h2] = o;
    } else if (t < 128) {
        int tt = t - 64;
        float4 a = sm2[0][tt], b = sm2[1][tt], c = sm2[2][tt], d = sm2[3][tt];
        float4 o;
        o.x = (a.x + b.x) + (c.x + d.x);
        o.y = (a.y + b.y) + (c.y + d.y);
        o.z = (a.z + b.z) + (c.z + d.z);
        o.w = (a.w + b.w) + (c.w + d.w);
        int qq = blockIdx.x * 64 + tt;
        int b2 = qq >> 14, h2 = qq & (HW24 - 1);
        reinterpret_cast<float4*>(g_n2)[(batch0 + b2) * HW24 + h2] = o;
    }
}

// ---------------------------------------------------------------------------
// K2 (per chunk): 3x3 conv (pad 1) + bias on n1/n2, write only r1 = c1/(c1+c2).
// n arrays are L2-resident (1 MB per chunk).
// ---------------------------------------------------------------------------
__global__ __launch_bounds__(256) void k_conv_ratio(const float* __restrict__ w,
                                                    const float* __restrict__ bias,
                                                    int batch0) {
    int i = blockIdx.x * blockDim.x + threadIdx.x;   // [0, CPIX)
    if (i >= CPIX) return;
    int bl = i >> 16;            // / HW2
    int hw = i & (HW2 - 1);
    int y  = hw >> 8;
    int x  = hw & (HWD - 1);
    int b  = batch0 + bl;

    float w00 = __ldg(w+0), w01 = __ldg(w+1), w02 = __ldg(w+2);
    float w10 = __ldg(w+3), w11 = __ldg(w+4), w12 = __ldg(w+5);
    float w20 = __ldg(w+6), w21 = __ldg(w+7), w22 = __ldg(w+8);
    float bv  = __ldg(bias);

    const float* n1 = g_n1 + b * HW2;
    const float* n2 = g_n2 + b * HW2;

    float c1 = 0.f, c2 = 0.f;
    bool ym = (y > 0), yp = (y < HWD - 1);
    bool xm = (x > 0), xp = (x < HWD - 1);
    int r0 = (y - 1) * HWD, r1r = y * HWD, r2r = (y + 1) * HWD;

    if (ym) {
        if (xm) { c1 += w00 * n1[r0 + x - 1]; c2 += w00 * n2[r0 + x - 1]; }
                  c1 += w01 * n1[r0 + x    ]; c2 += w01 * n2[r0 + x    ];
        if (xp) { c1 += w02 * n1[r0 + x + 1]; c2 += w02 * n2[r0 + x + 1]; }
    }
    if (xm) { c1 += w10 * n1[r1r + x - 1]; c2 += w10 * n2[r1r + x - 1]; }
              c1 += w11 * n1[r1r + x    ]; c2 += w11 * n2[r1r + x    ];
    if (xp) { c1 += w12 * n1[r1r + x + 1]; c2 += w12 * n2[r1r + x + 1]; }
    if (yp) {
        if (xm) { c1 += w20 * n1[r2r + x - 1]; c2 += w20 * n2[r2r + x - 1]; }
                  c1 += w21 * n1[r2r + x    ]; c2 += w21 * n2[r2r + x    ];
        if (xp) { c1 += w22 * n1[r2r + x + 1]; c2 += w22 * n2[r2r + x + 1]; }
    }
    c1 += bv;
    c2 += bv;
    g_r1[b * HW2 + hw] = c1 / (c1 + c2);
}

// ---------------------------------------------------------------------------
// K3 (per chunk): out = x1*r1 + x2*(1-r1).
// Thread owns one pixel-quad x one 16-channel group: r1 loaded ONCE, x loads
// are last-use (__ldcs, evict-first), out stores streaming (__stcs) so the
// L2-resident x chunk (just read by K1) isn't evicted before we re-read it.
// ---------------------------------------------------------------------------
__global__ __launch_bounds__(256) void k_blend(const float4* __restrict__ x1,
                                               const float4* __restrict__ x2,
                                               float4* __restrict__ out,
                                               int batch0) {
    int i = blockIdx.x * blockDim.x + threadIdx.x;   // [0, 4*CQ)
    int q = i & (CQ - 1);        // pixel-quad within chunk  (CQ = 1<<15)
    int g = i >> 15;             // channel group 0..3
    int bl  = q >> 14;
    int hw4 = q & (HW24 - 1);

    float4 r1 = __ldg(&reinterpret_cast<const float4*>(g_r1)[(batch0 + bl) * HW24 + hw4]);
    float4 r2 = make_float4(1.f - r1.x, 1.f - r1.y, 1.f - r1.z, 1.f - r1.w);

    size_t base = ((size_t)(batch0 + bl) * NC + g * 16) * HW24 + hw4;
#pragma unroll 4
    for (int c = 0; c < 16; ++c) {
        float4 a = __ldcs(x1 + base + (size_t)c * HW24);
        float4 d = __ldcs(x2 + base + (size_t)c * HW24);
        float4 o;
        o.x = a.x * r1.x + d.x * r2.x;
        o.y = a.y * r1.y + d.y * r2.y;
        o.z = a.z * r1.z + d.z * r2.z;
        o.w = a.w * r1.w + d.w * r2.w;
        __stcs(out + base + (size_t)c * HW24, o);
    }
}

extern "C" void kernel_launch(void* const* d_in, const int* in_sizes, int n_in,
                              void* d_out, int out_size) {
    const float4* x1 = (const float4*)d_in[0];
    const float4* x2 = (const float4*)d_in[1];
    const float*  w  = (const float*)d_in[2];
    const float*  bv = (const float*)d_in[3];
    float4* out = (float4*)d_out;

    for (int c = 0; c < NCHUNK; ++c) {
        int batch0 = c * BPC;
        k_norm      <<<CQ / 64,        256>>>(x1, x2, batch0);
        k_conv_ratio<<<CPIX / 256,     256>>>(w, bv, batch0);
        k_blend     <<<(4 * CQ) / 256, 256>>>(x1, x2, out, batch0);
    }
}

// round 4
// speedup vs baseline: 1.0218x; 1.0218x over previous
#include <cuda_runtime.h>

#define HWD   256
#define HW2   65536            // HWD*HWD
#define NB    8
#define NC    64
#define NPIX  (NB*HW2)         // 524288
#define HW24  16384            // HW2/4
#define BPC   2                // batches per chunk (67 MB of x per chunk < 126 MB L2)
#define NCHUNK (NB/BPC)        // 4
#define CQ    (BPC*HW24)       // pixel-quads per chunk = 32768
#define CPIX  (BPC*HW2)        // pixels per chunk     = 131072

// Scratch (static device globals — allocation-free)
__device__ float g_n1[NPIX];
__device__ float g_n2[NPIX];
__device__ float g_r1[NPIX];

// ---------------------------------------------------------------------------
// K1 (per chunk): per-pixel channel L1 norms of x1 and x2.
// 4-way channel split within a block (64 pixel-quads x 4 groups of 16 ch),
// smem combine. 16-ch loop FULLY UNROLLED -> up to 32 loads in flight per
// thread (MLP is what bounds DRAM% here, per R3 regression).
// ---------------------------------------------------------------------------
__global__ __launch_bounds__(256) void k_norm(const float4* __restrict__ x1,
                                              const float4* __restrict__ x2,
                                              int batch0) {
    __shared__ float4 sm1[4][64];
    __shared__ float4 sm2[4][64];
    int t = threadIdx.x;
    int p = t & 63;                 // pixel-quad within block
    int g = t >> 6;                 // channel group 0..3
    int q = blockIdx.x * 64 + p;    // [0, CQ)
    int bl  = q >> 14;              // / HW24
    int hw4 = q & (HW24 - 1);
    size_t base = ((size_t)(batch0 + bl) * NC + g * 16) * HW24 + hw4;
    const float4* p1 = x1 + base;
    const float4* p2 = x2 + base;

    float4 s1 = make_float4(0.f, 0.f, 0.f, 0.f);
    float4 s2 = make_float4(0.f, 0.f, 0.f, 0.f);
#pragma unroll
    for (int c = 0; c < 16; ++c) {
        float4 a = p1[(size_t)c * HW24];
        float4 d = p2[(size_t)c * HW24];
        s1.x += fabsf(a.x); s1.y += fabsf(a.y); s1.z += fabsf(a.z); s1.w += fabsf(a.w);
        s2.x += fabsf(d.x); s2.y += fabsf(d.y); s2.z += fabsf(d.z); s2.w += fabsf(d.w);
    }
    sm1[g][p] = s1;
    sm2[g][p] = s2;
    __syncthreads();

    if (t < 64) {
        float4 a = sm1[0][t], b = sm1[1][t], c = sm1[2][t], d = sm1[3][t];
        float4 o;
        o.x = (a.x + b.x) + (c.x + d.x);
        o.y = (a.y + b.y) + (c.y + d.y);
        o.z = (a.z + b.z) + (c.z + d.z);
        o.w = (a.w + b.w) + (c.w + d.w);
        int qq = blockIdx.x * 64 + t;
        int b2 = qq >> 14, h2 = qq & (HW24 - 1);
        reinterpret_cast<float4*>(g_n1)[(batch0 + b2) * HW24 + h2] = o;
    } else if (t < 128) {
        int tt = t - 64;
        float4 a = sm2[0][tt], b = sm2[1][tt], c = sm2[2][tt], d = sm2[3][tt];
        float4 o;
        o.x = (a.x + b.x) + (c.x + d.x);
        o.y = (a.y + b.y) + (c.y + d.y);
        o.z = (a.z + b.z) + (c.z + d.z);
        o.w = (a.w + b.w) + (c.w + d.w);
        int qq = blockIdx.x * 64 + tt;
        int b2 = qq >> 14, h2 = qq & (HW24 - 1);
        reinterpret_cast<float4*>(g_n2)[(batch0 + b2) * HW24 + h2] = o;
    }
}

// ---------------------------------------------------------------------------
// K2 (per chunk): 3x3 conv (pad 1) + bias on n1/n2, write only r1 = c1/(c1+c2).
// n arrays are L2-resident (1 MB per chunk).
// ---------------------------------------------------------------------------
__global__ __launch_bounds__(256) void k_conv_ratio(const float* __restrict__ w,
                                                    const float* __restrict__ bias,
                                                    int batch0) {
    int i = blockIdx.x * blockDim.x + threadIdx.x;   // [0, CPIX)
    if (i >= CPIX) return;
    int bl = i >> 16;            // / HW2
    int hw = i & (HW2 - 1);
    int y  = hw >> 8;
    int x  = hw & (HWD - 1);
    int b  = batch0 + bl;

    float w00 = __ldg(w+0), w01 = __ldg(w+1), w02 = __ldg(w+2);
    float w10 = __ldg(w+3), w11 = __ldg(w+4), w12 = __ldg(w+5);
    float w20 = __ldg(w+6), w21 = __ldg(w+7), w22 = __ldg(w+8);
    float bv  = __ldg(bias);

    const float* n1 = g_n1 + b * HW2;
    const float* n2 = g_n2 + b * HW2;

    float c1 = 0.f, c2 = 0.f;
    bool ym = (y > 0), yp = (y < HWD - 1);
    bool xm = (x > 0), xp = (x < HWD - 1);
    int r0 = (y - 1) * HWD, r1r = y * HWD, r2r = (y + 1) * HWD;

    if (ym) {
        if (xm) { c1 += w00 * n1[r0 + x - 1]; c2 += w00 * n2[r0 + x - 1]; }
                  c1 += w01 * n1[r0 + x    ]; c2 += w01 * n2[r0 + x    ];
        if (xp) { c1 += w02 * n1[r0 + x + 1]; c2 += w02 * n2[r0 + x + 1]; }
    }
    if (xm) { c1 += w10 * n1[r1r + x - 1]; c2 += w10 * n2[r1r + x - 1]; }
              c1 += w11 * n1[r1r + x    ]; c2 += w11 * n2[r1r + x    ];
    if (xp) { c1 += w12 * n1[r1r + x + 1]; c2 += w12 * n2[r1r + x + 1]; }
    if (yp) {
        if (xm) { c1 += w20 * n1[r2r + x - 1]; c2 += w20 * n2[r2r + x - 1]; }
                  c1 += w21 * n1[r2r + x    ]; c2 += w21 * n2[r2r + x    ];
        if (xp) { c1 += w22 * n1[r2r + x + 1]; c2 += w22 * n2[r2r + x + 1]; }
    }
    c1 += bv;
    c2 += bv;
    g_r1[b * HW2 + hw] = c1 / (c1 + c2);
}

// ---------------------------------------------------------------------------
// K3 (per chunk): out = x1*r1 + x2*(1-r1).
// Thread owns one pixel-quad x one 16-channel group: r1 loaded ONCE, x loads
// are last-use (__ldcs), out stores streaming (__stcs). unroll 8 for MLP.
// ---------------------------------------------------------------------------
__global__ __launch_bounds__(256) void k_blend(const float4* __restrict__ x1,
                                               const float4* __restrict__ x2,
                                               float4* __restrict__ out,
                                               int batch0) {
    int i = blockIdx.x * blockDim.x + threadIdx.x;   // [0, 4*CQ)
    int q = i & (CQ - 1);        // pixel-quad within chunk  (CQ = 1<<15)
    int g = i >> 15;             // channel group 0..3
    int bl  = q >> 14;
    int hw4 = q & (HW24 - 1);

    float4 r1 = __ldg(&reinterpret_cast<const float4*>(g_r1)[(batch0 + bl) * HW24 + hw4]);
    float4 r2 = make_float4(1.f - r1.x, 1.f - r1.y, 1.f - r1.z, 1.f - r1.w);

    size_t base = ((size_t)(batch0 + bl) * NC + g * 16) * HW24 + hw4;
#pragma unroll 8
    for (int c = 0; c < 16; ++c) {
        float4 a = __ldcs(x1 + base + (size_t)c * HW24);
        float4 d = __ldcs(x2 + base + (size_t)c * HW24);
        float4 o;
        o.x = a.x * r1.x + d.x * r2.x;
        o.y = a.y * r1.y + d.y * r2.y;
        o.z = a.z * r1.z + d.z * r2.z;
        o.w = a.w * r1.w + d.w * r2.w;
        __stcs(out + base + (size_t)c * HW24, o);
    }
}

extern "C" void kernel_launch(void* const* d_in, const int* in_sizes, int n_in,
                              void* d_out, int out_size) {
    const float4* x1 = (const float4*)d_in[0];
    const float4* x2 = (const float4*)d_in[1];
    const float*  w  = (const float*)d_in[2];
    const float*  bv = (const float*)d_in[3];
    float4* out = (float4*)d_out;

    for (int c = 0; c < NCHUNK; ++c) {
        int batch0 = c * BPC;
        k_norm      <<<CQ / 64,        256>>>(x1, x2, batch0);
        k_conv_ratio<<<CPIX / 256,     256>>>(w, bv, batch0);
        k_blend     <<<(4 * CQ) / 256, 256>>>(x1, x2, out, batch0);
    }
}

// round 5
// speedup vs baseline: 1.0994x; 1.0760x over previous
#include <cuda_runtime.h>

#define HWD   256
#define HW2   65536            // HWD*HWD
#define NB    8
#define NC    64
#define NPIX  (NB*HW2)         // 524288
#define HW24  16384            // HW2/4
#define BPC   2                // batches per chunk (67 MB of x per chunk)
#define NCHUNK (NB/BPC)        // 4
#define CQ    (BPC*HW24)       // pixel-quads per chunk = 32768
#define CPIX  (BPC*HW2)        // pixels per chunk     = 131072

// Scratch (static device globals — allocation-free)
__device__ float g_n1[NPIX];
__device__ float g_n2[NPIX];
__device__ float g_r1[NPIX];

// ---------------------------------------------------------------------------
// K1 (per chunk): per-pixel channel L1 norms of x1 and x2.
// 4-way channel split within a block (64 pixel-quads x 4 groups of 16 ch),
// smem combine; fully unrolled channel loop.
// ---------------------------------------------------------------------------
__global__ __launch_bounds__(256) void k_norm(const float4* __restrict__ x1,
                                              const float4* __restrict__ x2,
                                              int batch0) {
    __shared__ float4 sm1[4][64];
    __shared__ float4 sm2[4][64];
    int t = threadIdx.x;
    int p = t & 63;                 // pixel-quad within block
    int g = t >> 6;                 // channel group 0..3
    int q = blockIdx.x * 64 + p;    // [0, CQ)
    int bl  = q >> 14;              // / HW24
    int hw4 = q & (HW24 - 1);
    size_t base = ((size_t)(batch0 + bl) * NC + g * 16) * HW24 + hw4;
    const float4* p1 = x1 + base;
    const float4* p2 = x2 + base;

    float4 s1 = make_float4(0.f, 0.f, 0.f, 0.f);
    float4 s2 = make_float4(0.f, 0.f, 0.f, 0.f);
#pragma unroll
    for (int c = 0; c < 16; ++c) {
        float4 a = p1[(size_t)c * HW24];
        float4 d = p2[(size_t)c * HW24];
        s1.x += fabsf(a.x); s1.y += fabsf(a.y); s1.z += fabsf(a.z); s1.w += fabsf(a.w);
        s2.x += fabsf(d.x); s2.y += fabsf(d.y); s2.z += fabsf(d.z); s2.w += fabsf(d.w);
    }
    sm1[g][p] = s1;
    sm2[g][p] = s2;
    __syncthreads();

    if (t < 64) {
        float4 a = sm1[0][t], b = sm1[1][t], c = sm1[2][t], d = sm1[3][t];
        float4 o;
        o.x = (a.x + b.x) + (c.x + d.x);
        o.y = (a.y + b.y) + (c.y + d.y);
        o.z = (a.z + b.z) + (c.z + d.z);
        o.w = (a.w + b.w) + (c.w + d.w);
        int qq = blockIdx.x * 64 + t;
        int b2 = qq >> 14, h2 = qq & (HW24 - 1);
        reinterpret_cast<float4*>(g_n1)[(batch0 + b2) * HW24 + h2] = o;
    } else if (t < 128) {
        int tt = t - 64;
        float4 a = sm2[0][tt], b = sm2[1][tt], c = sm2[2][tt], d = sm2[3][tt];
        float4 o;
        o.x = (a.x + b.x) + (c.x + d.x);
        o.y = (a.y + b.y) + (c.y + d.y);
        o.z = (a.z + b.z) + (c.z + d.z);
        o.w = (a.w + b.w) + (c.w + d.w);
        int qq = blockIdx.x * 64 + tt;
        int b2 = qq >> 14, h2 = qq & (HW24 - 1);
        reinterpret_cast<float4*>(g_n2)[(batch0 + b2) * HW24 + h2] = o;
    }
}

// ---------------------------------------------------------------------------
// K2 (per chunk): 3x3 conv (pad 1) + bias on n1/n2, write r1 = c1/(c1+c2).
// ---------------------------------------------------------------------------
__global__ __launch_bounds__(256) void k_conv_ratio(const float* __restrict__ w,
                                                    const float* __restrict__ bias,
                                                    int batch0) {
    int i = blockIdx.x * blockDim.x + threadIdx.x;   // [0, CPIX)
    if (i >= CPIX) return;
    int bl = i >> 16;            // / HW2
    int hw = i & (HW2 - 1);
    int y  = hw >> 8;
    int x  = hw & (HWD - 1);
    int b  = batch0 + bl;

    float w00 = __ldg(w+0), w01 = __ldg(w+1), w02 = __ldg(w+2);
    float w10 = __ldg(w+3), w11 = __ldg(w+4), w12 = __ldg(w+5);
    float w20 = __ldg(w+6), w21 = __ldg(w+7), w22 = __ldg(w+8);
    float bv  = __ldg(bias);

    const float* n1 = g_n1 + b * HW2;
    const float* n2 = g_n2 + b * HW2;

    float c1 = 0.f, c2 = 0.f;
    bool ym = (y > 0), yp = (y < HWD - 1);
    bool xm = (x > 0), xp = (x < HWD - 1);
    int r0 = (y - 1) * HWD, r1r = y * HWD, r2r = (y + 1) * HWD;

    if (ym) {
        if (xm) { c1 += w00 * n1[r0 + x - 1]; c2 += w00 * n2[r0 + x - 1]; }
                  c1 += w01 * n1[r0 + x    ]; c2 += w01 * n2[r0 + x    ];
        if (xp) { c1 += w02 * n1[r0 + x + 1]; c2 += w02 * n2[r0 + x + 1]; }
    }
    if (xm) { c1 += w10 * n1[r1r + x - 1]; c2 += w10 * n2[r1r + x - 1]; }
              c1 += w11 * n1[r1r + x    ]; c2 += w11 * n2[r1r + x    ];
    if (xp) { c1 += w12 * n1[r1r + x + 1]; c2 += w12 * n2[r1r + x + 1]; }
    if (yp) {
        if (xm) { c1 += w20 * n1[r2r + x - 1]; c2 += w20 * n2[r2r + x - 1]; }
                  c1 += w21 * n1[r2r + x    ]; c2 += w21 * n2[r2r + x    ];
        if (xp) { c1 += w22 * n1[r2r + x + 1]; c2 += w22 * n2[r2r + x + 1]; }
    }
    c1 += bv;
    c2 += bv;
    g_r1[b * HW2 + hw] = c1 / (c1 + c2);
}

// ---------------------------------------------------------------------------
// K3 (per chunk): out = x1*r1 + x2*(1-r1).  r1 loaded once per 16 channels,
// x loads last-use (__ldcs), streaming stores (__stcs).
// ---------------------------------------------------------------------------
__global__ __launch_bounds__(256) void k_blend(const float4* __restrict__ x1,
                                               const float4* __restrict__ x2,
                                               float4* __restrict__ out,
                                               int batch0) {
    int i = blockIdx.x * blockDim.x + threadIdx.x;   // [0, 4*CQ)
    int q = i & (CQ - 1);        // pixel-quad within chunk  (CQ = 1<<15)
    int g = i >> 15;             // channel group 0..3
    int bl  = q >> 14;
    int hw4 = q & (HW24 - 1);

    float4 r1 = __ldg(&reinterpret_cast<const float4*>(g_r1)[(batch0 + bl) * HW24 + hw4]);
    float4 r2 = make_float4(1.f - r1.x, 1.f - r1.y, 1.f - r1.z, 1.f - r1.w);

    size_t base = ((size_t)(batch0 + bl) * NC + g * 16) * HW24 + hw4;
#pragma unroll 8
    for (int c = 0; c < 16; ++c) {
        float4 a = __ldcs(x1 + base + (size_t)c * HW24);
        float4 d = __ldcs(x2 + base + (size_t)c * HW24);
        float4 o;
        o.x = a.x * r1.x + d.x * r2.x;
        o.y = a.y * r1.y + d.y * r2.y;
        o.z = a.z * r1.z + d.z * r2.z;
        o.w = a.w * r1.w + d.w * r2.w;
        __stcs(out + base + (size_t)c * HW24, o);
    }
}

// ---------------------------------------------------------------------------
// Pipelined launch: norm/conv on the captured (default) stream, blend on a
// non-blocking side stream joined via events so blend_c overlaps norm_{c+1}.
// Streams/events are created once (host resources only — no device memory).
// ---------------------------------------------------------------------------
struct PipeRes {
    cudaStream_t s2;
    cudaEvent_t  evConv[NCHUNK];
    cudaEvent_t  evBlendLast;
    PipeRes() {
        cudaStreamCreateWithFlags(&s2, cudaStreamNonBlocking);
        for (int c = 0; c < NCHUNK; ++c)
            cudaEventCreateWithFlags(&evConv[c], cudaEventDisableTiming);
        cudaEventCreateWithFlags(&evBlendLast, cudaEventDisableTiming);
    }
};

extern "C" void kernel_launch(void* const* d_in, const int* in_sizes, int n_in,
                              void* d_out, int out_size) {
    static PipeRes R;   // created on first (correctness) call, before capture

    const float4* x1 = (const float4*)d_in[0];
    const float4* x2 = (const float4*)d_in[1];
    const float*  w  = (const float*)d_in[2];
    const float*  bv = (const float*)d_in[3];
    float4* out = (float4*)d_out;

    for (int c = 0; c < NCHUNK; ++c) {
        int batch0 = c * BPC;
        // producer side: default (captured) stream
        k_norm      <<<CQ / 64,    256, 0, 0>>>(x1, x2, batch0);
        k_conv_ratio<<<CPIX / 256, 256, 0, 0>>>(w, bv, batch0);
        cudaEventRecord(R.evConv[c], 0);
        // consumer side: side stream, forked off the captured stream
        cudaStreamWaitEvent(R.s2, R.evConv[c], 0);
        k_blend<<<(4 * CQ) / 256, 256, 0, R.s2>>>(x1, x2, out, batch0);
    }
    // join: blends execute in-order on s2, so the last one gates completion
    cudaEventRecord(R.evBlendLast, R.s2);
    cudaStreamWaitEvent(0, R.evBlendLast, 0);
}